// round 1
// baseline (speedup 1.0000x reference)
#include <cuda_runtime.h>
#include <math.h>

// ---------------------------------------------------------------------------
// Net_66468913873438: GCN(512->64)+ReLU -> GatedGraphConv(H=64, 2 layers)
//                     -> GCN(64->16) -> log_softmax
// N = 100000 nodes, E = 3200000 edges.
// ---------------------------------------------------------------------------

#define NMAX 100000

// Scratch (static device globals; no allocation in kernel_launch).
__device__ __align__(16) float g_deg [NMAX];
__device__ __align__(16) float g_dinv[NMAX];
__device__ __align__(16) float g_hs  [NMAX * 64];  // dinv-scaled linear output (gcn1)
__device__ __align__(16) float g_acc [NMAX * 64];  // scatter accumulator
__device__ __align__(16) float g_x   [NMAX * 64];  // node state
__device__ __align__(16) float g_m   [NMAX * 64];  // gated-graph messages
__device__ __align__(16) float g_hs3 [NMAX * 16];  // dinv-scaled linear output (gcn2)
__device__ __align__(16) float g_WT  [64 * 384];   // [WihT | WhhT] as [k][j]

// ---------------------------------------------------------------------------
// Small utility kernels
// ---------------------------------------------------------------------------

__global__ void k_fill1(float* __restrict__ p, int n) {
    int i = blockIdx.x * 256 + threadIdx.x;
    if (i < n) p[i] = 1.0f;  // self-loop weight
}

__global__ void k_zero4(float4* __restrict__ p, int n4) {
    int i = blockIdx.x * 256 + threadIdx.x;
    if (i < n4) p[i] = make_float4(0.f, 0.f, 0.f, 0.f);
}

__global__ void k_deg_accum(const int* __restrict__ col, const float* __restrict__ w,
                            float* __restrict__ deg, int E) {
    int e = blockIdx.x * 256 + threadIdx.x;
    if (e < E) atomicAdd(&deg[col[e]], w[e]);
}

__global__ void k_dinv(const float* __restrict__ deg, float* __restrict__ dinv, int n) {
    int i = blockIdx.x * 256 + threadIdx.x;
    if (i < n) {
        float d = deg[i];
        dinv[i] = (d > 0.f) ? rsqrtf(d) : 0.f;
    }
}

// Build WT[k][j]: j in [0,192) -> Wih[j][k], j in [192,384) -> Whh[j-192][k]
__global__ void k_transpose_w(const float* __restrict__ Wih, const float* __restrict__ Whh,
                              float* __restrict__ WT) {
    int idx = blockIdx.x * 256 + threadIdx.x;
    if (idx >= 64 * 384) return;
    int k = idx / 384, j = idx % 384;
    float v = (j < 192) ? Wih[j * 64 + k] : Whh[(j - 192) * 64 + k];
    WT[idx] = v;
}

// ---------------------------------------------------------------------------
// GEMM: out[n, 0..63] = scale(n) * sum_k A[n,k] * W[k, j]   (W has 64 cols)
// BM=64, BN=64, BK=32, 256 threads, 4x4 register tile per thread.
// ---------------------------------------------------------------------------
__global__ void gemm_n64(const float* __restrict__ A, const float* __restrict__ W,
                         float* __restrict__ out, const float* __restrict__ dinv,
                         int nrows, int K, int use_dinv) {
    __shared__ float xs[32][65];   // [k][m], +1 pad -> conflict-free
    __shared__ float ws[32][64];   // [k][n]

    const int block_m = blockIdx.x * 64;
    const int tid = threadIdx.x;
    const int tx = tid & 15;       // col group (4 cols)
    const int ty = tid >> 4;       // row group (4 rows)

    float acc[4][4];
#pragma unroll
    for (int i = 0; i < 4; i++)
#pragma unroll
        for (int j = 0; j < 4; j++) acc[i][j] = 0.f;

    for (int k0 = 0; k0 < K; k0 += 32) {
        // load A tile (64 rows x 32 k), coalesced along k
#pragma unroll
        for (int i = 0; i < 8; i++) {
            int idx = i * 256 + tid;
            int kk = idx & 31;
            int mm = idx >> 5;
            int gm = block_m + mm;
            float v = (gm < nrows) ? A[(long)gm * K + (k0 + kk)] : 0.f;
            xs[kk][mm] = v;
        }
        // load W tile (32 k x 64 n), coalesced along n
#pragma unroll
        for (int i = 0; i < 8; i++) {
            int idx = i * 256 + tid;
            int nn = idx & 63;
            int kk = idx >> 6;
            ws[kk][nn] = W[(long)(k0 + kk) * 64 + nn];
        }
        __syncthreads();

#pragma unroll
        for (int k = 0; k < 32; k++) {
            float a[4], b[4];
#pragma unroll
            for (int i = 0; i < 4; i++) a[i] = xs[k][ty * 4 + i];
#pragma unroll
            for (int j = 0; j < 4; j++) b[j] = ws[k][tx * 4 + j];
#pragma unroll
            for (int i = 0; i < 4; i++)
#pragma unroll
                for (int j = 0; j < 4; j++) acc[i][j] += a[i] * b[j];
        }
        __syncthreads();
    }

#pragma unroll
    for (int i = 0; i < 4; i++) {
        int gm = block_m + ty * 4 + i;
        if (gm >= nrows) continue;
        float s = use_dinv ? dinv[gm] : 1.0f;
#pragma unroll
        for (int j = 0; j < 4; j++)
            out[(long)gm * 64 + tx * 4 + j] = s * acc[i][j];
    }
}

// ---------------------------------------------------------------------------
// Edge scatter, 64-wide features: acc[col[e]] += w[e] * feat[row[e]]
// 16 threads per edge, float4 gathers, scalar f32 reductions.
// ---------------------------------------------------------------------------
__global__ void scatter64(const int* __restrict__ row, const int* __restrict__ col,
                          const float* __restrict__ w, const float* __restrict__ feat,
                          float* __restrict__ acc, int E) {
    long gid = (long)blockIdx.x * 256 + threadIdx.x;
    long e = gid >> 4;
    int q = (int)(gid & 15);
    if (e >= E) return;
    int s = row[e];
    int d = col[e];
    float ww = w[e];
    float4 v = ((const float4*)feat)[(long)s * 16 + q];
    float* dst = acc + ((long)d * 16 + q) * 4;
    atomicAdd(dst + 0, ww * v.x);
    atomicAdd(dst + 1, ww * v.y);
    atomicAdd(dst + 2, ww * v.z);
    atomicAdd(dst + 3, ww * v.w);
}

// 16-wide variant (4 threads per edge)
__global__ void scatter16(const int* __restrict__ row, const int* __restrict__ col,
                          const float* __restrict__ w, const float* __restrict__ feat,
                          float* __restrict__ acc, int E) {
    long gid = (long)blockIdx.x * 256 + threadIdx.x;
    long e = gid >> 2;
    int q = (int)(gid & 3);
    if (e >= E) return;
    int s = row[e];
    int d = col[e];
    float ww = w[e];
    float4 v = ((const float4*)feat)[(long)s * 4 + q];
    float* dst = acc + ((long)d * 4 + q) * 4;
    atomicAdd(dst + 0, ww * v.x);
    atomicAdd(dst + 1, ww * v.y);
    atomicAdd(dst + 2, ww * v.z);
    atomicAdd(dst + 3, ww * v.w);
}

// ---------------------------------------------------------------------------
// GCN1 finalize: x = relu(dinv[n]*(acc + hs) + b1[f])
// (acc is the neighbor sum of dinv[src]-scaled features; hs covers self loop)
// ---------------------------------------------------------------------------
__global__ void k_fin1(const float* __restrict__ acc, const float* __restrict__ hs,
                       const float* __restrict__ dinv, const float* __restrict__ b1,
                       float* __restrict__ xout, int n) {
    int i = blockIdx.x * 256 + threadIdx.x;
    if (i >= n * 64) return;
    int node = i >> 6;
    int f = i & 63;
    float v = dinv[node] * (acc[i] + hs[i]) + __ldg(&b1[f]);
    xout[i] = v > 0.f ? v : 0.f;
}

// ---------------------------------------------------------------------------
// Fused GRU cell: x = GRU(agg, x) with Wih/Whh cached (transposed) in smem.
// Block: 256 threads = 4 groups x 64 feature lanes; block handles 16 nodes,
// each group register-tiles 4 nodes.
// ---------------------------------------------------------------------------
#define GRU_SMEM ((64 * 384 + 2 * 16 * 64) * 4)

__global__ void gru_kernel(const float* __restrict__ agg, float* __restrict__ x,
                           const float* __restrict__ WT,
                           const float* __restrict__ bih, const float* __restrict__ bhh,
                           int nrows) {
    extern __shared__ float sm[];
    float* wt = sm;                 // [64][384]
    float* ag = sm + 64 * 384;      // [16][64]
    float* xv = ag + 16 * 64;       // [16][64]

    const int tid = threadIdx.x;
    const int n0 = blockIdx.x * 16;

    for (int i = tid; i < 64 * 384; i += 256) wt[i] = WT[i];
    for (int i = tid; i < 16 * 64; i += 256) {
        int nn = n0 + (i >> 6);
        float a = 0.f, xx = 0.f;
        if (nn < nrows) {
            a  = agg[(long)nn * 64 + (i & 63)];
            xx = x  [(long)nn * 64 + (i & 63)];
        }
        ag[i] = a;
        xv[i] = xx;
    }
    __syncthreads();

    const int f = tid & 63;
    const int g = tid >> 6;  // 0..3

    float air[4] = {}, aiz[4] = {}, ain[4] = {};
    float ahr[4] = {}, ahz[4] = {}, ahn[4] = {};

#pragma unroll 8
    for (int k = 0; k < 64; k++) {
        const float* wr = wt + k * 384;
        float wir = wr[f], wiz = wr[64 + f], win = wr[128 + f];
        float whr = wr[192 + f], whz = wr[256 + f], whn = wr[320 + f];
#pragma unroll
        for (int t = 0; t < 4; t++) {
            float a  = ag[(g * 4 + t) * 64 + k];
            float xx = xv[(g * 4 + t) * 64 + k];
            air[t] += wir * a;  aiz[t] += wiz * a;  ain[t] += win * a;
            ahr[t] += whr * xx; ahz[t] += whz * xx; ahn[t] += whn * xx;
        }
    }

    float bir = __ldg(&bih[f]), biz = __ldg(&bih[64 + f]), bin = __ldg(&bih[128 + f]);
    float bhr = __ldg(&bhh[f]), bhz = __ldg(&bhh[64 + f]), bhn = __ldg(&bhh[128 + f]);

#pragma unroll
    for (int t = 0; t < 4; t++) {
        int nn = n0 + g * 4 + t;
        if (nn >= nrows) continue;
        float r = 1.f / (1.f + expf(-(air[t] + bir + ahr[t] + bhr)));
        float z = 1.f / (1.f + expf(-(aiz[t] + biz + ahz[t] + bhz)));
        float ng = tanhf(ain[t] + bin + r * (ahn[t] + bhn));
        float xo = xv[(g * 4 + t) * 64 + f];
        x[(long)nn * 64 + f] = (1.f - z) * ng + z * xo;
    }
}

// ---------------------------------------------------------------------------
// GCN2 linear: hs3[n, c] = dinv[n] * sum_k x[n,k] * W2[k,c]   (c < 16)
// ---------------------------------------------------------------------------
__global__ void gemm_out16(const float* __restrict__ x, const float* __restrict__ W2,
                           const float* __restrict__ dinv, float* __restrict__ hs3,
                           int nrows) {
    __shared__ float w2s[64 * 16];
    int tid = threadIdx.x;
    for (int i = tid; i < 64 * 16; i += 256) w2s[i] = W2[i];
    __syncthreads();

    int node = blockIdx.x * 16 + (tid >> 4);
    int c = tid & 15;
    if (node >= nrows) return;
    const float* xr = x + (long)node * 64;
    float s = 0.f;
#pragma unroll
    for (int k = 0; k < 64; k++) s += xr[k] * w2s[k * 16 + c];
    hs3[(long)node * 16 + c] = dinv[node] * s;
}

// ---------------------------------------------------------------------------
// GCN2 finalize + log_softmax over 16 classes. One thread per node.
// ---------------------------------------------------------------------------
__global__ void k_final(const float* __restrict__ acc3, const float* __restrict__ hs3,
                        const float* __restrict__ dinv, const float* __restrict__ b2,
                        float* __restrict__ out, int nrows) {
    int n = blockIdx.x * 256 + threadIdx.x;
    if (n >= nrows) return;
    float di = dinv[n];
    const float4* a4 = (const float4*)(acc3 + (long)n * 16);
    const float4* h4 = (const float4*)(hs3 + (long)n * 16);
    float v[16];
#pragma unroll
    for (int i = 0; i < 4; i++) {
        float4 a = a4[i];
        float4 h = h4[i];
        v[i * 4 + 0] = di * (a.x + h.x) + __ldg(&b2[i * 4 + 0]);
        v[i * 4 + 1] = di * (a.y + h.y) + __ldg(&b2[i * 4 + 1]);
        v[i * 4 + 2] = di * (a.z + h.z) + __ldg(&b2[i * 4 + 2]);
        v[i * 4 + 3] = di * (a.w + h.w) + __ldg(&b2[i * 4 + 3]);
    }
    float mx = v[0];
#pragma unroll
    for (int c = 1; c < 16; c++) mx = fmaxf(mx, v[c]);
    float sum = 0.f;
#pragma unroll
    for (int c = 0; c < 16; c++) sum += expf(v[c] - mx);
    float l = mx + logf(sum);
    float4* o4 = (float4*)(out + (long)n * 16);
#pragma unroll
    for (int i = 0; i < 4; i++) {
        float4 o;
        o.x = v[i * 4 + 0] - l;
        o.y = v[i * 4 + 1] - l;
        o.z = v[i * 4 + 2] - l;
        o.w = v[i * 4 + 3] - l;
        o4[i] = o;
    }
}

// ---------------------------------------------------------------------------
// Launch sequence
// ---------------------------------------------------------------------------
extern "C" void kernel_launch(void* const* d_in, const int* in_sizes, int n_in,
                              void* d_out, int out_size) {
    const float* x   = (const float*)d_in[0];
    const int*   ei  = (const int*)d_in[1];
    const float* ew  = (const float*)d_in[2];
    const float* W1  = (const float*)d_in[3];
    const float* b1  = (const float*)d_in[4];
    const float* Wg  = (const float*)d_in[5];
    const float* Wih = (const float*)d_in[6];
    const float* Whh = (const float*)d_in[7];
    const float* bih = (const float*)d_in[8];
    const float* bhh = (const float*)d_in[9];
    const float* W2  = (const float*)d_in[10];
    const float* b2  = (const float*)d_in[11];
    float* out = (float*)d_out;

    const int N = in_sizes[0] / 512;
    const int E = in_sizes[2];
    const int* row = ei;        // edge_index[0] (source)
    const int* col = ei + E;    // edge_index[1] (destination)

    float *p_deg, *p_dinv, *p_hs, *p_acc, *p_x, *p_m, *p_hs3, *p_WT;
    cudaGetSymbolAddress((void**)&p_deg,  g_deg);
    cudaGetSymbolAddress((void**)&p_dinv, g_dinv);
    cudaGetSymbolAddress((void**)&p_hs,   g_hs);
    cudaGetSymbolAddress((void**)&p_acc,  g_acc);
    cudaGetSymbolAddress((void**)&p_x,    g_x);
    cudaGetSymbolAddress((void**)&p_m,    g_m);
    cudaGetSymbolAddress((void**)&p_hs3,  g_hs3);
    cudaGetSymbolAddress((void**)&p_WT,   g_WT);

    cudaFuncSetAttribute(gru_kernel, cudaFuncAttributeMaxDynamicSharedMemorySize, GRU_SMEM);

    const int nblkN   = (N + 255) / 256;
    const int nblkE   = (E + 255) / 256;
    const int nblkG   = (N + 63) / 64;      // gemm row tiles
    const int nblk16  = (N + 15) / 16;
    const int nblkS64 = (int)(((long)E * 16 + 255) / 256);
    const int nblkS16 = (int)(((long)E * 4 + 255) / 256);
    const int nblkZ64 = (N * 16 + 255) / 256;   // N*64 floats = N*16 float4
    const int nblkZ16 = (N * 4 + 255) / 256;
    const int nblkNF  = (N * 64 + 255) / 256;

    // --- degree / normalization (shared by both GCN layers) ---
    k_fill1<<<nblkN, 256>>>(p_deg, N);
    k_deg_accum<<<nblkE, 256>>>(col, ew, p_deg, E);
    k_dinv<<<nblkN, 256>>>(p_deg, p_dinv, N);

    // --- GRU weight transpose (once per launch) ---
    k_transpose_w<<<(64 * 384 + 255) / 256, 256>>>(Wih, Whh, p_WT);

    // --- GCN layer 1: hs = dinv * (x @ W1); acc = scatter; x = relu(...) ---
    gemm_n64<<<nblkG, 256>>>(x, W1, p_hs, p_dinv, N, 512, 1);
    k_zero4<<<nblkZ64, 256>>>((float4*)p_acc, N * 16);
    scatter64<<<nblkS64, 256>>>(row, col, ew, p_hs, p_acc, E);
    k_fin1<<<nblkNF, 256>>>(p_acc, p_hs, p_dinv, b1, p_x, N);

    // --- GatedGraphConv: 2 layers ---
    for (int l = 0; l < 2; l++) {
        gemm_n64<<<nblkG, 256>>>(p_x, Wg + (long)l * 64 * 64, p_m, p_dinv, N, 64, 0);
        k_zero4<<<nblkZ64, 256>>>((float4*)p_acc, N * 16);
        scatter64<<<nblkS64, 256>>>(row, col, ew, p_m, p_acc, E);
        gru_kernel<<<nblk16, 256, GRU_SMEM>>>(p_acc, p_x, p_WT, bih, bhh, N);
    }

    // --- GCN layer 2 + log_softmax ---
    gemm_out16<<<nblk16, 256>>>(p_x, W2, p_dinv, p_hs3, N);
    k_zero4<<<nblkZ16, 256>>>((float4*)p_acc, N * 4);
    scatter16<<<nblkS16, 256>>>(row, col, ew, p_hs3, p_acc, E);
    k_final<<<nblkN, 256>>>(p_acc, p_hs3, p_dinv, b2, out, N);
}

// round 2
// speedup vs baseline: 1.8558x; 1.8558x over previous
#include <cuda_runtime.h>
#include <math.h>

// ---------------------------------------------------------------------------
// Net_66468913873438: GCN(512->64)+ReLU -> GatedGraphConv(H=64, 2 layers)
//                     -> GCN(64->16) -> log_softmax
// N = 100000 nodes, E = 3200000 edges.
// R2: per-launch CSR (dst-sorted) turns all edge scatters (atomics) into
//     conflict-free gathers.
// ---------------------------------------------------------------------------

#define NMAX 100000
#define EMAX 3200000
#define CHUNK 1024

// Scratch (static device globals; no allocation in kernel_launch).
__device__ __align__(16) float  g_deg   [NMAX];
__device__ __align__(16) float  g_dinv  [NMAX];
__device__ __align__(16) float  g_hs    [NMAX * 64];
__device__ __align__(16) float  g_acc   [NMAX * 64];
__device__ __align__(16) float  g_x     [NMAX * 64];
__device__ __align__(16) float  g_m     [NMAX * 64];
__device__ __align__(16) float  g_hs3   [NMAX * 16];
__device__ __align__(16) float  g_WT    [64 * 384];
// CSR
__device__ __align__(16) int    g_cnt   [NMAX];
__device__ __align__(16) int    g_start [NMAX];
__device__ __align__(16) int    g_cursor[NMAX];
__device__ __align__(16) int    g_csum  [128];
__device__ __align__(16) float2 g_sw    [EMAX];   // (src as int bits, weight)

// ---------------------------------------------------------------------------
// Small utility kernels
// ---------------------------------------------------------------------------
__global__ void k_fill1(float* __restrict__ p, int n) {
    int i = blockIdx.x * 256 + threadIdx.x;
    if (i < n) p[i] = 1.0f;
}
__global__ void k_zeroi(int* __restrict__ p, int n) {
    int i = blockIdx.x * 256 + threadIdx.x;
    if (i < n) p[i] = 0;
}
__global__ void k_copyi(const int* __restrict__ a, int* __restrict__ b, int n) {
    int i = blockIdx.x * 256 + threadIdx.x;
    if (i < n) b[i] = a[i];
}
__global__ void k_deg_accum(const int* __restrict__ col, const float* __restrict__ w,
                            float* __restrict__ deg, int E) {
    int e = blockIdx.x * 256 + threadIdx.x;
    if (e < E) atomicAdd(&deg[col[e]], w[e]);
}
__global__ void k_dinv(const float* __restrict__ deg, float* __restrict__ dinv, int n) {
    int i = blockIdx.x * 256 + threadIdx.x;
    if (i < n) {
        float d = deg[i];
        dinv[i] = (d > 0.f) ? rsqrtf(d) : 0.f;
    }
}
__global__ void k_transpose_w(const float* __restrict__ Wih, const float* __restrict__ Whh,
                              float* __restrict__ WT) {
    int idx = blockIdx.x * 256 + threadIdx.x;
    if (idx >= 64 * 384) return;
    int k = idx / 384, j = idx % 384;
    WT[idx] = (j < 192) ? Wih[j * 64 + k] : Whh[(j - 192) * 64 + k];
}

// ---------------------------------------------------------------------------
// CSR build: histogram -> chunked exclusive scan -> reorder
// ---------------------------------------------------------------------------
__global__ void k_hist(const int* __restrict__ col, int* __restrict__ cnt, int E) {
    int e = blockIdx.x * 256 + threadIdx.x;
    if (e < E) atomicAdd(&cnt[col[e]], 1);
}

__global__ void k_scan_chunk(const int* __restrict__ cnt, int* __restrict__ start,
                             int* __restrict__ csum, int n) {
    __shared__ int sm[CHUNK];
    int base = blockIdx.x * CHUNK;
    int t = threadIdx.x;
    int v = (base + t < n) ? cnt[base + t] : 0;
    sm[t] = v;
    __syncthreads();
#pragma unroll
    for (int off = 1; off < CHUNK; off <<= 1) {
        int x = (t >= off) ? sm[t - off] : 0;
        __syncthreads();
        sm[t] += x;
        __syncthreads();
    }
    if (base + t < n) start[base + t] = sm[t] - v;   // exclusive within chunk
    if (t == CHUNK - 1) csum[blockIdx.x] = sm[t];
}

__global__ void k_scan_sums(int* __restrict__ csum, int nch) {
    if (blockIdx.x == 0 && threadIdx.x == 0) {
        int acc = 0;
        for (int i = 0; i < nch; i++) { int v = csum[i]; csum[i] = acc; acc += v; }
    }
}

__global__ void k_scan_add(int* __restrict__ start, const int* __restrict__ csum, int n) {
    int i = blockIdx.x * 256 + threadIdx.x;
    if (i < n) start[i] += csum[i >> 10];
}

__global__ void k_reorder(const int* __restrict__ row, const int* __restrict__ col,
                          const float* __restrict__ w, int* __restrict__ cursor,
                          float2* __restrict__ sw, int E) {
    int e = blockIdx.x * 256 + threadIdx.x;
    if (e >= E) return;
    int d = col[e];
    int pos = atomicAdd(&cursor[d], 1);
    sw[pos] = make_float2(__int_as_float(row[e]), w[e]);
}

// ---------------------------------------------------------------------------
// GEMM: out[n, 0..63] = scale(n) * sum_k A[n,k] * W[k, j]
// ---------------------------------------------------------------------------
__global__ void gemm_n64(const float* __restrict__ A, const float* __restrict__ W,
                         float* __restrict__ out, const float* __restrict__ dinv,
                         int nrows, int K, int use_dinv) {
    __shared__ float xs[32][65];
    __shared__ float ws[32][64];

    const int block_m = blockIdx.x * 64;
    const int tid = threadIdx.x;
    const int tx = tid & 15;
    const int ty = tid >> 4;

    float acc[4][4];
#pragma unroll
    for (int i = 0; i < 4; i++)
#pragma unroll
        for (int j = 0; j < 4; j++) acc[i][j] = 0.f;

    for (int k0 = 0; k0 < K; k0 += 32) {
#pragma unroll
        for (int i = 0; i < 8; i++) {
            int idx = i * 256 + tid;
            int kk = idx & 31;
            int mm = idx >> 5;
            int gm = block_m + mm;
            xs[kk][mm] = (gm < nrows) ? A[(long)gm * K + (k0 + kk)] : 0.f;
        }
#pragma unroll
        for (int i = 0; i < 8; i++) {
            int idx = i * 256 + tid;
            ws[idx >> 6][idx & 63] = W[(long)(k0 + (idx >> 6)) * 64 + (idx & 63)];
        }
        __syncthreads();
#pragma unroll
        for (int k = 0; k < 32; k++) {
            float a[4], b[4];
#pragma unroll
            for (int i = 0; i < 4; i++) a[i] = xs[k][ty * 4 + i];
#pragma unroll
            for (int j = 0; j < 4; j++) b[j] = ws[k][tx * 4 + j];
#pragma unroll
            for (int i = 0; i < 4; i++)
#pragma unroll
                for (int j = 0; j < 4; j++) acc[i][j] += a[i] * b[j];
        }
        __syncthreads();
    }

#pragma unroll
    for (int i = 0; i < 4; i++) {
        int gm = block_m + ty * 4 + i;
        if (gm >= nrows) continue;
        float s = use_dinv ? dinv[gm] : 1.0f;
#pragma unroll
        for (int j = 0; j < 4; j++)
            out[(long)gm * 64 + tx * 4 + j] = s * acc[i][j];
    }
}

// ---------------------------------------------------------------------------
// CSR gather, 64-wide features: acc[d] = sum_j w_j * feat[src_j]
// 16 threads per destination, float4 lanes, unroll-2 for MLP.
// mode 0: out = acc
// mode 1: out = relu(dinv[d]*(acc + hs[d]) + b1)   (GCN1 finalize fused)
// ---------------------------------------------------------------------------
__global__ void gather64(const int* __restrict__ start, const int* __restrict__ cnt,
                         const float2* __restrict__ sw, const float4* __restrict__ feat4,
                         const float4* __restrict__ hs4, const float* __restrict__ dinv,
                         const float* __restrict__ b1, float4* __restrict__ out4,
                         int N, int mode) {
    int gid = blockIdx.x * 256 + threadIdx.x;
    int d = gid >> 4;
    int q = gid & 15;
    if (d >= N) return;

    int j = start[d];
    int end = j + cnt[d];
    float4 acc = make_float4(0.f, 0.f, 0.f, 0.f);

    for (; j + 1 < end; j += 2) {
        float2 p0 = __ldg(&sw[j]);
        float2 p1 = __ldg(&sw[j + 1]);
        int s0 = __float_as_int(p0.x);
        int s1 = __float_as_int(p1.x);
        float4 v0 = feat4[s0 * 16 + q];
        float4 v1 = feat4[s1 * 16 + q];
        acc.x += p0.y * v0.x; acc.y += p0.y * v0.y;
        acc.z += p0.y * v0.z; acc.w += p0.y * v0.w;
        acc.x += p1.y * v1.x; acc.y += p1.y * v1.y;
        acc.z += p1.y * v1.z; acc.w += p1.y * v1.w;
    }
    if (j < end) {
        float2 p = __ldg(&sw[j]);
        int s = __float_as_int(p.x);
        float4 v = feat4[s * 16 + q];
        acc.x += p.y * v.x; acc.y += p.y * v.y;
        acc.z += p.y * v.z; acc.w += p.y * v.w;
    }

    int o = d * 16 + q;
    if (mode == 1) {
        float di = dinv[d];
        float4 h = hs4[o];
        float4 bb = ((const float4*)b1)[q];
        acc.x = fmaxf(di * (acc.x + h.x) + bb.x, 0.f);
        acc.y = fmaxf(di * (acc.y + h.y) + bb.y, 0.f);
        acc.z = fmaxf(di * (acc.z + h.z) + bb.z, 0.f);
        acc.w = fmaxf(di * (acc.w + h.w) + bb.w, 0.f);
    }
    out4[o] = acc;
}

// 16-wide CSR gather: 4 threads per destination.
__global__ void gather16(const int* __restrict__ start, const int* __restrict__ cnt,
                         const float2* __restrict__ sw, const float4* __restrict__ feat4,
                         float4* __restrict__ out4, int N) {
    int gid = blockIdx.x * 256 + threadIdx.x;
    int d = gid >> 2;
    int q = gid & 3;
    if (d >= N) return;

    int j = start[d];
    int end = j + cnt[d];
    float4 acc = make_float4(0.f, 0.f, 0.f, 0.f);

    for (; j + 1 < end; j += 2) {
        float2 p0 = __ldg(&sw[j]);
        float2 p1 = __ldg(&sw[j + 1]);
        float4 v0 = feat4[__float_as_int(p0.x) * 4 + q];
        float4 v1 = feat4[__float_as_int(p1.x) * 4 + q];
        acc.x += p0.y * v0.x; acc.y += p0.y * v0.y;
        acc.z += p0.y * v0.z; acc.w += p0.y * v0.w;
        acc.x += p1.y * v1.x; acc.y += p1.y * v1.y;
        acc.z += p1.y * v1.z; acc.w += p1.y * v1.w;
    }
    if (j < end) {
        float2 p = __ldg(&sw[j]);
        float4 v = feat4[__float_as_int(p.x) * 4 + q];
        acc.x += p.y * v.x; acc.y += p.y * v.y;
        acc.z += p.y * v.z; acc.w += p.y * v.w;
    }
    out4[d * 4 + q] = acc;
}

// ---------------------------------------------------------------------------
// Fused GRU cell (unchanged from R1)
// ---------------------------------------------------------------------------
#define GRU_SMEM ((64 * 384 + 2 * 16 * 64) * 4)

__global__ void gru_kernel(const float* __restrict__ agg, float* __restrict__ x,
                           const float* __restrict__ WT,
                           const float* __restrict__ bih, const float* __restrict__ bhh,
                           int nrows) {
    extern __shared__ float sm[];
    float* wt = sm;
    float* ag = sm + 64 * 384;
    float* xv = ag + 16 * 64;

    const int tid = threadIdx.x;
    const int n0 = blockIdx.x * 16;

    for (int i = tid; i < 64 * 384; i += 256) wt[i] = WT[i];
    for (int i = tid; i < 16 * 64; i += 256) {
        int nn = n0 + (i >> 6);
        float a = 0.f, xx = 0.f;
        if (nn < nrows) {
            a  = agg[(long)nn * 64 + (i & 63)];
            xx = x  [(long)nn * 64 + (i & 63)];
        }
        ag[i] = a;
        xv[i] = xx;
    }
    __syncthreads();

    const int f = tid & 63;
    const int g = tid >> 6;

    float air[4] = {}, aiz[4] = {}, ain[4] = {};
    float ahr[4] = {}, ahz[4] = {}, ahn[4] = {};

#pragma unroll 8
    for (int k = 0; k < 64; k++) {
        const float* wr = wt + k * 384;
        float wir = wr[f], wiz = wr[64 + f], win = wr[128 + f];
        float whr = wr[192 + f], whz = wr[256 + f], whn = wr[320 + f];
#pragma unroll
        for (int t = 0; t < 4; t++) {
            float a  = ag[(g * 4 + t) * 64 + k];
            float xx = xv[(g * 4 + t) * 64 + k];
            air[t] += wir * a;  aiz[t] += wiz * a;  ain[t] += win * a;
            ahr[t] += whr * xx; ahz[t] += whz * xx; ahn[t] += whn * xx;
        }
    }

    float bir = __ldg(&bih[f]), biz = __ldg(&bih[64 + f]), bin = __ldg(&bih[128 + f]);
    float bhr = __ldg(&bhh[f]), bhz = __ldg(&bhh[64 + f]), bhn = __ldg(&bhh[128 + f]);

#pragma unroll
    for (int t = 0; t < 4; t++) {
        int nn = n0 + g * 4 + t;
        if (nn >= nrows) continue;
        float r = 1.f / (1.f + expf(-(air[t] + bir + ahr[t] + bhr)));
        float z = 1.f / (1.f + expf(-(aiz[t] + biz + ahz[t] + bhz)));
        float ng = tanhf(ain[t] + bin + r * (ahn[t] + bhn));
        float xo = xv[(g * 4 + t) * 64 + f];
        x[(long)nn * 64 + f] = (1.f - z) * ng + z * xo;
    }
}

// ---------------------------------------------------------------------------
// GCN2 linear + finalize (unchanged from R1)
// ---------------------------------------------------------------------------
__global__ void gemm_out16(const float* __restrict__ x, const float* __restrict__ W2,
                           const float* __restrict__ dinv, float* __restrict__ hs3,
                           int nrows) {
    __shared__ float w2s[64 * 16];
    int tid = threadIdx.x;
    for (int i = tid; i < 64 * 16; i += 256) w2s[i] = W2[i];
    __syncthreads();

    int node = blockIdx.x * 16 + (tid >> 4);
    int c = tid & 15;
    if (node >= nrows) return;
    const float* xr = x + (long)node * 64;
    float s = 0.f;
#pragma unroll
    for (int k = 0; k < 64; k++) s += xr[k] * w2s[k * 16 + c];
    hs3[(long)node * 16 + c] = dinv[node] * s;
}

__global__ void k_final(const float* __restrict__ acc3, const float* __restrict__ hs3,
                        const float* __restrict__ dinv, const float* __restrict__ b2,
                        float* __restrict__ out, int nrows) {
    int n = blockIdx.x * 256 + threadIdx.x;
    if (n >= nrows) return;
    float di = dinv[n];
    const float4* a4 = (const float4*)(acc3 + (long)n * 16);
    const float4* h4 = (const float4*)(hs3 + (long)n * 16);
    float v[16];
#pragma unroll
    for (int i = 0; i < 4; i++) {
        float4 a = a4[i];
        float4 h = h4[i];
        v[i * 4 + 0] = di * (a.x + h.x) + __ldg(&b2[i * 4 + 0]);
        v[i * 4 + 1] = di * (a.y + h.y) + __ldg(&b2[i * 4 + 1]);
        v[i * 4 + 2] = di * (a.z + h.z) + __ldg(&b2[i * 4 + 2]);
        v[i * 4 + 3] = di * (a.w + h.w) + __ldg(&b2[i * 4 + 3]);
    }
    float mx = v[0];
#pragma unroll
    for (int c = 1; c < 16; c++) mx = fmaxf(mx, v[c]);
    float sum = 0.f;
#pragma unroll
    for (int c = 0; c < 16; c++) sum += expf(v[c] - mx);
    float l = mx + logf(sum);
    float4* o4 = (float4*)(out + (long)n * 16);
#pragma unroll
    for (int i = 0; i < 4; i++) {
        float4 o;
        o.x = v[i * 4 + 0] - l;
        o.y = v[i * 4 + 1] - l;
        o.z = v[i * 4 + 2] - l;
        o.w = v[i * 4 + 3] - l;
        o4[i] = o;
    }
}

// ---------------------------------------------------------------------------
// Launch sequence
// ---------------------------------------------------------------------------
extern "C" void kernel_launch(void* const* d_in, const int* in_sizes, int n_in,
                              void* d_out, int out_size) {
    const float* x   = (const float*)d_in[0];
    const int*   ei  = (const int*)d_in[1];
    const float* ew  = (const float*)d_in[2];
    const float* W1  = (const float*)d_in[3];
    const float* b1  = (const float*)d_in[4];
    const float* Wg  = (const float*)d_in[5];
    const float* Wih = (const float*)d_in[6];
    const float* Whh = (const float*)d_in[7];
    const float* bih = (const float*)d_in[8];
    const float* bhh = (const float*)d_in[9];
    const float* W2  = (const float*)d_in[10];
    const float* b2  = (const float*)d_in[11];
    float* out = (float*)d_out;

    const int N = in_sizes[0] / 512;
    const int E = in_sizes[2];
    const int* row = ei;
    const int* col = ei + E;

    float *p_deg, *p_dinv, *p_hs, *p_acc, *p_x, *p_m, *p_hs3, *p_WT;
    int *p_cnt, *p_start, *p_cursor, *p_csum;
    float2* p_sw;
    cudaGetSymbolAddress((void**)&p_deg,    g_deg);
    cudaGetSymbolAddress((void**)&p_dinv,   g_dinv);
    cudaGetSymbolAddress((void**)&p_hs,     g_hs);
    cudaGetSymbolAddress((void**)&p_acc,    g_acc);
    cudaGetSymbolAddress((void**)&p_x,      g_x);
    cudaGetSymbolAddress((void**)&p_m,      g_m);
    cudaGetSymbolAddress((void**)&p_hs3,    g_hs3);
    cudaGetSymbolAddress((void**)&p_WT,     g_WT);
    cudaGetSymbolAddress((void**)&p_cnt,    g_cnt);
    cudaGetSymbolAddress((void**)&p_start,  g_start);
    cudaGetSymbolAddress((void**)&p_cursor, g_cursor);
    cudaGetSymbolAddress((void**)&p_csum,   g_csum);
    cudaGetSymbolAddress((void**)&p_sw,     g_sw);

    cudaFuncSetAttribute(gru_kernel, cudaFuncAttributeMaxDynamicSharedMemorySize, GRU_SMEM);

    const int nblkN  = (N + 255) / 256;
    const int nblkE  = (E + 255) / 256;
    const int nblkG  = (N + 63) / 64;
    const int nblk16 = (N + 15) / 16;
    const int nchunks = (N + CHUNK - 1) / CHUNK;
    const int nblkG64 = (N * 16 + 255) / 256;   // gather64 threads
    const int nblkG16 = (N * 4 + 255) / 256;    // gather16 threads

    // --- degree / normalization ---
    k_fill1<<<nblkN, 256>>>(p_deg, N);
    k_deg_accum<<<nblkE, 256>>>(col, ew, p_deg, E);
    k_dinv<<<nblkN, 256>>>(p_deg, p_dinv, N);

    // --- CSR build (dst-sorted) ---
    k_zeroi<<<nblkN, 256>>>(p_cnt, N);
    k_hist<<<nblkE, 256>>>(col, p_cnt, E);
    k_scan_chunk<<<nchunks, CHUNK>>>(p_cnt, p_start, p_csum, N);
    k_scan_sums<<<1, 32>>>(p_csum, nchunks);
    k_scan_add<<<nblkN, 256>>>(p_start, p_csum, N);
    k_copyi<<<nblkN, 256>>>(p_start, p_cursor, N);
    k_reorder<<<nblkE, 256>>>(row, col, ew, p_cursor, p_sw, E);

    // --- GRU weight transpose ---
    k_transpose_w<<<(64 * 384 + 255) / 256, 256>>>(Wih, Whh, p_WT);

    // --- GCN layer 1 (gather fuses relu/dinv/bias finalize) ---
    gemm_n64<<<nblkG, 256>>>(x, W1, p_hs, p_dinv, N, 512, 1);
    gather64<<<nblkG64, 256>>>(p_start, p_cnt, p_sw, (const float4*)p_hs,
                               (const float4*)p_hs, p_dinv, b1, (float4*)p_x, N, 1);

    // --- GatedGraphConv: 2 layers ---
    for (int l = 0; l < 2; l++) {
        gemm_n64<<<nblkG, 256>>>(p_x, Wg + (long)l * 64 * 64, p_m, p_dinv, N, 64, 0);
        gather64<<<nblkG64, 256>>>(p_start, p_cnt, p_sw, (const float4*)p_m,
                                   (const float4*)p_m, p_dinv, b1, (float4*)p_acc, N, 0);
        gru_kernel<<<nblk16, 256, GRU_SMEM>>>(p_acc, p_x, p_WT, bih, bhh, N);
    }

    // --- GCN layer 2 + log_softmax ---
    gemm_out16<<<nblk16, 256>>>(p_x, W2, p_dinv, p_hs3, N);
    gather16<<<nblkG16, 256>>>(p_start, p_cnt, p_sw, (const float4*)p_hs3,
                               (float4*)p_acc, N);
    k_final<<<nblkN, 256>>>(p_acc, p_hs3, p_dinv, b2, out, N);
}

// round 5
// speedup vs baseline: 2.5476x; 1.3727x over previous
#include <cuda_runtime.h>
#include <math.h>
#include <stdint.h>

// ---------------------------------------------------------------------------
// Net_66468913873438: GCN(512->64)+ReLU -> GatedGraphConv(H=64, 2 layers)
//                     -> GCN(64->16) -> log_softmax
// N = 100000, E = 3200000.
// R5: R4 (mma.sync tf32x3 GEMMs) with smem-OOB fix: B-tile index in mma_step
//     is chunk-local (bk0), A-tile index global (ak0).
// ---------------------------------------------------------------------------

#define NMAX 100000
#define EMAX 3200000
#define CHUNK 1024

// Scratch (static device globals).
__device__ __align__(16) float  g_deg   [NMAX];
__device__ __align__(16) float  g_dinv  [NMAX];
__device__ __align__(16) float  g_hs    [NMAX * 64];   // gemm1 out / msg buffer
__device__ __align__(16) float  g_acc   [NMAX * 64];   // gather accumulator
__device__ __align__(16) float  g_x     [NMAX * 64];   // node state
__device__ __align__(16) float  g_hs3   [NMAX * 16];
__device__ __align__(16) float  g_gi    [NMAX * 192];
__device__ __align__(16) float  g_big   [NMAX * 256];  // [m(0:64) | gh(64:256)]
__device__ __align__(16) float  g_W1T   [64 * 512];
__device__ __align__(16) float  g_WB    [2 * 256 * 64]; // [WgT_l | Whh] K-major
// CSR
__device__ __align__(16) int    g_cnt   [NMAX];
__device__ __align__(16) int    g_start [NMAX];
__device__ __align__(16) int    g_cursor[NMAX];
__device__ __align__(16) int    g_csum  [128];
__device__ __align__(16) float2 g_sw    [EMAX];   // (src as int bits, weight)

// ---------------------------------------------------------------------------
// tf32 mma.sync helpers (sm_80 base ISA; compiles for plain sm_103 target)
// ---------------------------------------------------------------------------
__device__ __forceinline__ float fhi(float a) {
    return __int_as_float(__float_as_int(a) & 0xFFFFE000u);
}

struct AFrag { uint32_t h[4]; uint32_t l[4]; };

__device__ __forceinline__ void mma8(float c[4], const uint32_t a[4],
                                     uint32_t b0, uint32_t b1) {
    asm volatile(
        "mma.sync.aligned.m16n8k8.row.col.f32.tf32.tf32.f32 "
        "{%0,%1,%2,%3}, {%4,%5,%6,%7}, {%8,%9}, {%0,%1,%2,%3};"
        : "+f"(c[0]), "+f"(c[1]), "+f"(c[2]), "+f"(c[3])
        : "r"(a[0]), "r"(a[1]), "r"(a[2]), "r"(a[3]), "r"(b0), "r"(b1));
}

__device__ __forceinline__ void load_afrag(const float* As, int stride, int rbase,
                                           int k0, int g, int tg, AFrag& f) {
    float a0 = As[(rbase + g) * stride + k0 + tg];
    float a1 = As[(rbase + g + 8) * stride + k0 + tg];
    float a2 = As[(rbase + g) * stride + k0 + tg + 4];
    float a3 = As[(rbase + g + 8) * stride + k0 + tg + 4];
    float h0 = fhi(a0), h1 = fhi(a1), h2 = fhi(a2), h3 = fhi(a3);
    f.h[0] = __float_as_uint(h0); f.l[0] = __float_as_uint(fhi(a0 - h0));
    f.h[1] = __float_as_uint(h1); f.l[1] = __float_as_uint(fhi(a1 - h1));
    f.h[2] = __float_as_uint(h2); f.l[2] = __float_as_uint(fhi(a2 - h2));
    f.h[3] = __float_as_uint(h3); f.l[3] = __float_as_uint(fhi(a3 - h3));
}

// one k8 step: warp tile 32 rows (2 m-frags) x 64 cols (8 n-frags), tf32x3.
// ak0 = k offset into As row (global within A tile);
// bk0 = k offset into Bh/Bl row (chunk-local, < 32).
__device__ __forceinline__ void mma_step(const float* As, int astride, int wr,
                                         int ak0, const float* Bh, const float* Bl,
                                         int bk0, int g, int tg, float c[2][8][4]) {
    AFrag fa[2];
    load_afrag(As, astride, wr, ak0, g, tg, fa[0]);
    load_afrag(As, astride, wr + 16, ak0, g, tg, fa[1]);
#pragma unroll
    for (int nt = 0; nt < 8; nt++) {
        int nr = (nt * 8 + g) * 36 + bk0;
        uint32_t bh0 = __float_as_uint(Bh[nr + tg]);
        uint32_t bh1 = __float_as_uint(Bh[nr + tg + 4]);
        uint32_t bl0 = __float_as_uint(Bl[nr + tg]);
        uint32_t bl1 = __float_as_uint(Bl[nr + tg + 4]);
#pragma unroll
        for (int mt = 0; mt < 2; mt++) {
            mma8(c[mt][nt], fa[mt].h, bh0, bh1);
            mma8(c[mt][nt], fa[mt].l, bh0, bh1);
            mma8(c[mt][nt], fa[mt].h, bl0, bl1);
        }
    }
}

// ---------------------------------------------------------------------------
// Small utility kernels
// ---------------------------------------------------------------------------
__global__ void k_init(float* __restrict__ deg, int* __restrict__ cnt, int n) {
    int i = blockIdx.x * 256 + threadIdx.x;
    if (i < n) { deg[i] = 1.0f; cnt[i] = 0; }
}
__global__ void k_deg_hist(const int* __restrict__ col, const float* __restrict__ w,
                           float* __restrict__ deg, int* __restrict__ cnt, int E) {
    int e = blockIdx.x * 256 + threadIdx.x;
    if (e < E) {
        int d = col[e];
        atomicAdd(&deg[d], w[e]);
        atomicAdd(&cnt[d], 1);
    }
}
__global__ void k_dinv(const float* __restrict__ deg, float* __restrict__ dinv, int n) {
    int i = blockIdx.x * 256 + threadIdx.x;
    if (i < n) {
        float d = deg[i];
        dinv[i] = (d > 0.f) ? rsqrtf(d) : 0.f;
    }
}
__global__ void k_T512(const float* __restrict__ W, float* __restrict__ WT) {
    int idx = blockIdx.x * 256 + threadIdx.x;
    if (idx >= 512 * 64) return;
    int k = idx / 64, j = idx % 64;
    WT[j * 512 + k] = W[idx];
}
__global__ void k_buildWB(const float* __restrict__ Wg, const float* __restrict__ Whh,
                          float* __restrict__ WB) {
    int idx = blockIdx.x * 256 + threadIdx.x;
    if (idx >= 2 * 256 * 64) return;
    int l = idx / (256 * 64);
    int rem = idx % (256 * 64);
    int j = rem / 64, k = rem % 64;
    float v = (j < 64) ? Wg[l * 4096 + k * 64 + j] : Whh[(j - 64) * 64 + k];
    WB[idx] = v;
}

// ---------------------------------------------------------------------------
// CSR build
// ---------------------------------------------------------------------------
__global__ void k_scan_chunk(const int* __restrict__ cnt, int* __restrict__ start,
                             int* __restrict__ csum, int n) {
    __shared__ int sm[CHUNK];
    int base = blockIdx.x * CHUNK;
    int t = threadIdx.x;
    int v = (base + t < n) ? cnt[base + t] : 0;
    sm[t] = v;
    __syncthreads();
#pragma unroll
    for (int off = 1; off < CHUNK; off <<= 1) {
        int x = (t >= off) ? sm[t - off] : 0;
        __syncthreads();
        sm[t] += x;
        __syncthreads();
    }
    if (base + t < n) start[base + t] = sm[t] - v;
    if (t == CHUNK - 1) csum[blockIdx.x] = sm[t];
}
__global__ void k_scan_sums(int* __restrict__ csum, int nch) {
    if (blockIdx.x == 0 && threadIdx.x == 0) {
        int acc = 0;
        for (int i = 0; i < nch; i++) { int v = csum[i]; csum[i] = acc; acc += v; }
    }
}
__global__ void k_scan_add(int* __restrict__ start, int* __restrict__ cursor,
                           const int* __restrict__ csum, int n) {
    int i = blockIdx.x * 256 + threadIdx.x;
    if (i < n) {
        int s = start[i] + csum[i >> 10];
        start[i] = s;
        cursor[i] = s;
    }
}
__global__ void k_reorder(const int* __restrict__ row, const int* __restrict__ col,
                          const float* __restrict__ w, int* __restrict__ cursor,
                          float2* __restrict__ sw, int E) {
    int e = blockIdx.x * 256 + threadIdx.x;
    if (e >= E) return;
    int d = col[e];
    int pos = atomicAdd(&cursor[d], 1);
    sw[pos] = make_float2(__int_as_float(row[e]), w[e]);
}

// ---------------------------------------------------------------------------
// tf32x3 GEMM, K=512: hs[m,j] = dinv[m] * sum_k A[m,k] W1T[j,k]
// BM=256, BN=64, 256 threads (8 warps x warp-tile 32x64). K chunks of 32.
// ---------------------------------------------------------------------------
#define K512_AS 0
#define K512_BH (256 * 36)
#define K512_BL (K512_BH + 64 * 36)
#define K512_SMEM ((K512_BL + 64 * 36) * 4)

__global__ __launch_bounds__(256) void mma_k512(
    const float4* __restrict__ A4, const float4* __restrict__ B4,
    float* __restrict__ out, const float* __restrict__ dinv, int M)
{
    extern __shared__ float sm[];
    float* As = sm + K512_AS;
    float* Bh = sm + K512_BH;
    float* Bl = sm + K512_BL;

    int tid = threadIdx.x, wid = tid >> 5, lane = tid & 31;
    int g = lane >> 2, tg = lane & 3;
    int blk = blockIdx.x;
    int wr = wid * 32;

    float c[2][8][4];
#pragma unroll
    for (int mt = 0; mt < 2; mt++)
#pragma unroll
        for (int nt = 0; nt < 8; nt++)
#pragma unroll
            for (int i = 0; i < 4; i++) c[mt][nt][i] = 0.f;

    for (int kc = 0; kc < 16; kc++) {
        // A chunk: 256 rows x 32 k
#pragma unroll
        for (int it = 0; it < 8; it++) {
            int idx = it * 256 + tid;
            int r = idx >> 3, q = idx & 7;
            int gm = blk * 256 + r;
            float4 v = make_float4(0.f, 0.f, 0.f, 0.f);
            if (gm < M) v = A4[(size_t)gm * 128 + kc * 8 + q];
            *(float4*)(As + r * 36 + q * 4) = v;
        }
        // B chunk: 64 rows x 32 k, split hi/lo
#pragma unroll
        for (int it = 0; it < 2; it++) {
            int idx = it * 256 + tid;
            int r = idx >> 3, q = idx & 7;
            float4 v = B4[(size_t)r * 128 + kc * 8 + q];
            float4 h, l;
            h.x = fhi(v.x); l.x = fhi(v.x - h.x);
            h.y = fhi(v.y); l.y = fhi(v.y - h.y);
            h.z = fhi(v.z); l.z = fhi(v.z - h.z);
            h.w = fhi(v.w); l.w = fhi(v.w - h.w);
            *(float4*)(Bh + r * 36 + q * 4) = h;
            *(float4*)(Bl + r * 36 + q * 4) = l;
        }
        __syncthreads();
#pragma unroll
        for (int s = 0; s < 4; s++)
            mma_step(As, 36, wr, s * 8, Bh, Bl, s * 8, g, tg, c);
        __syncthreads();
    }

#pragma unroll
    for (int mt = 0; mt < 2; mt++) {
        int r0 = blk * 256 + wr + mt * 16 + g;
        int r1 = r0 + 8;
        float dv0 = (r0 < M) ? dinv[r0] : 0.f;
        float dv1 = (r1 < M) ? dinv[r1] : 0.f;
#pragma unroll
        for (int nt = 0; nt < 8; nt++) {
            int cb = nt * 8 + 2 * tg;
            if (r0 < M)
                *(float2*)(out + (size_t)r0 * 64 + cb) =
                    make_float2(dv0 * c[mt][nt][0], dv0 * c[mt][nt][1]);
            if (r1 < M)
                *(float2*)(out + (size_t)r1 * 64 + cb) =
                    make_float2(dv1 * c[mt][nt][2], dv1 * c[mt][nt][3]);
        }
    }
}

// ---------------------------------------------------------------------------
// tf32x3 GEMM, K=64: out[m, ct*64+j] = sum_k A[m,k] B[ct*64+j, k]
// A resident in smem (256x64, stride 68); B per (ct,kc) chunk pre-split.
// ---------------------------------------------------------------------------
#define K64_AS 0
#define K64_BH (256 * 68)
#define K64_BL (K64_BH + 64 * 36)
#define K64_SMEM ((K64_BL + 64 * 36) * 4)

__global__ __launch_bounds__(256) void mma_k64(
    const float4* __restrict__ A4, const float4* __restrict__ B4,
    float* __restrict__ out, int M, int ncols, int ostride)
{
    extern __shared__ float sm[];
    float* As = sm + K64_AS;
    float* Bh = sm + K64_BH;
    float* Bl = sm + K64_BL;

    int tid = threadIdx.x, wid = tid >> 5, lane = tid & 31;
    int g = lane >> 2, tg = lane & 3;
    int blk = blockIdx.x;
    int wr = wid * 32;

    // A: 256 x 64 resident
#pragma unroll
    for (int it = 0; it < 16; it++) {
        int idx = it * 256 + tid;
        int r = idx >> 4, q = idx & 15;
        int gm = blk * 256 + r;
        float4 v = make_float4(0.f, 0.f, 0.f, 0.f);
        if (gm < M) v = A4[(size_t)gm * 16 + q];
        *(float4*)(As + r * 68 + q * 4) = v;
    }
    __syncthreads();

    int ntilesc = ncols >> 6;
    for (int ct = 0; ct < ntilesc; ct++) {
        float c[2][8][4];
#pragma unroll
        for (int mt = 0; mt < 2; mt++)
#pragma unroll
            for (int nt = 0; nt < 8; nt++)
#pragma unroll
                for (int i = 0; i < 4; i++) c[mt][nt][i] = 0.f;

#pragma unroll
        for (int kc = 0; kc < 2; kc++) {
            // B chunk: rows ct*64..+63, k = kc*32..+31 (stored chunk-local)
#pragma unroll
            for (int it = 0; it < 2; it++) {
                int idx = it * 256 + tid;
                int r = idx >> 3, q = idx & 7;
                float4 v = B4[(size_t)(ct * 64 + r) * 16 + kc * 8 + q];
                float4 h, l;
                h.x = fhi(v.x); l.x = fhi(v.x - h.x);
                h.y = fhi(v.y); l.y = fhi(v.y - h.y);
                h.z = fhi(v.z); l.z = fhi(v.z - h.z);
                h.w = fhi(v.w); l.w = fhi(v.w - h.w);
                *(float4*)(Bh + r * 36 + q * 4) = h;
                *(float4*)(Bl + r * 36 + q * 4) = l;
            }
            __syncthreads();
#pragma unroll
            for (int s = 0; s < 4; s++)
                mma_step(As, 68, wr, kc * 32 + s * 8, Bh, Bl, s * 8, g, tg, c);
            __syncthreads();
        }

#pragma unroll
        for (int mt = 0; mt < 2; mt++) {
            int r0 = blk * 256 + wr + mt * 16 + g;
            int r1 = r0 + 8;
#pragma unroll
            for (int nt = 0; nt < 8; nt++) {
                int cb = ct * 64 + nt * 8 + 2 * tg;
                if (r0 < M)
                    *(float2*)(out + (size_t)r0 * ostride + cb) =
                        make_float2(c[mt][nt][0], c[mt][nt][1]);
                if (r1 < M)
                    *(float2*)(out + (size_t)r1 * ostride + cb) =
                        make_float2(c[mt][nt][2], c[mt][nt][3]);
            }
        }
    }
}

// ---------------------------------------------------------------------------
// CSR gathers
// ---------------------------------------------------------------------------
__global__ void gather64(const int* __restrict__ start, const int* __restrict__ cnt,
                         const float2* __restrict__ sw, const float4* __restrict__ feat4,
                         int sf4, const float4* __restrict__ hs4,
                         const float* __restrict__ dinv, const float* __restrict__ b1,
                         float4* __restrict__ out4, int N, int mode) {
    int gid = blockIdx.x * 256 + threadIdx.x;
    int d = gid >> 4;
    int q = gid & 15;
    if (d >= N) return;

    int j = start[d];
    int end = j + cnt[d];
    float4 acc = make_float4(0.f, 0.f, 0.f, 0.f);

    for (; j + 1 < end; j += 2) {
        float2 p0 = __ldg(&sw[j]);
        float2 p1 = __ldg(&sw[j + 1]);
        float4 v0 = feat4[(size_t)__float_as_int(p0.x) * sf4 + q];
        float4 v1 = feat4[(size_t)__float_as_int(p1.x) * sf4 + q];
        acc.x += p0.y * v0.x; acc.y += p0.y * v0.y;
        acc.z += p0.y * v0.z; acc.w += p0.y * v0.w;
        acc.x += p1.y * v1.x; acc.y += p1.y * v1.y;
        acc.z += p1.y * v1.z; acc.w += p1.y * v1.w;
    }
    if (j < end) {
        float2 p = __ldg(&sw[j]);
        float4 v = feat4[(size_t)__float_as_int(p.x) * sf4 + q];
        acc.x += p.y * v.x; acc.y += p.y * v.y;
        acc.z += p.y * v.z; acc.w += p.y * v.w;
    }

    int o = d * 16 + q;
    if (mode == 1) {
        float di = dinv[d];
        float4 h = hs4[o];
        float4 bb = ((const float4*)b1)[q];
        acc.x = fmaxf(di * (acc.x + h.x) + bb.x, 0.f);
        acc.y = fmaxf(di * (acc.y + h.y) + bb.y, 0.f);
        acc.z = fmaxf(di * (acc.z + h.z) + bb.z, 0.f);
        acc.w = fmaxf(di * (acc.w + h.w) + bb.w, 0.f);
    }
    out4[o] = acc;
}

__global__ void gather16(const int* __restrict__ start, const int* __restrict__ cnt,
                         const float2* __restrict__ sw, const float4* __restrict__ feat4,
                         float4* __restrict__ out4, int N) {
    int gid = blockIdx.x * 256 + threadIdx.x;
    int d = gid >> 2;
    int q = gid & 3;
    if (d >= N) return;

    int j = start[d];
    int end = j + cnt[d];
    float4 acc = make_float4(0.f, 0.f, 0.f, 0.f);

    for (; j + 1 < end; j += 2) {
        float2 p0 = __ldg(&sw[j]);
        float2 p1 = __ldg(&sw[j + 1]);
        float4 v0 = feat4[(size_t)__float_as_int(p0.x) * 4 + q];
        float4 v1 = feat4[(size_t)__float_as_int(p1.x) * 4 + q];
        acc.x += p0.y * v0.x; acc.y += p0.y * v0.y;
        acc.z += p0.y * v0.z; acc.w += p0.y * v0.w;
        acc.x += p1.y * v1.x; acc.y += p1.y * v1.y;
        acc.z += p1.y * v1.z; acc.w += p1.y * v1.w;
    }
    if (j < end) {
        float2 p = __ldg(&sw[j]);
        float4 v = feat4[(size_t)__float_as_int(p.x) * 4 + q];
        acc.x += p.y * v.x; acc.y += p.y * v.y;
        acc.z += p.y * v.z; acc.w += p.y * v.w;
    }
    out4[d * 4 + q] = acc;
}

// ---------------------------------------------------------------------------
// GRU elementwise combine: x = GRU(gi, gh, x); gh lives in g_big cols 64..255
// ---------------------------------------------------------------------------
__global__ void gru_combine(const float* __restrict__ gi, const float* __restrict__ big,
                            const float* __restrict__ bih, const float* __restrict__ bhh,
                            float* __restrict__ x, int n) {
    int i = blockIdx.x * 256 + threadIdx.x;
    if (i >= n * 64) return;
    int nd = i >> 6, f = i & 63;
    size_t bi = (size_t)nd * 192;
    size_t bh = (size_t)nd * 256 + 64;
    float r = 1.f / (1.f + expf(-(gi[bi + f] + __ldg(&bih[f]) +
                                  big[bh + f] + __ldg(&bhh[f]))));
    float z = 1.f / (1.f + expf(-(gi[bi + 64 + f] + __ldg(&bih[64 + f]) +
                                  big[bh + 64 + f] + __ldg(&bhh[64 + f]))));
    float ng = tanhf(gi[bi + 128 + f] + __ldg(&bih[128 + f]) +
                     r * (big[bh + 128 + f] + __ldg(&bhh[128 + f])));
    x[i] = (1.f - z) * ng + z * x[i];
}

// ---------------------------------------------------------------------------
// GCN2 linear + finalize
// ---------------------------------------------------------------------------
__global__ void gemm_out16(const float* __restrict__ x, const float* __restrict__ W2,
                           const float* __restrict__ dinv, float* __restrict__ hs3,
                           int nrows) {
    __shared__ float w2s[64 * 16];
    int tid = threadIdx.x;
    for (int i = tid; i < 64 * 16; i += 256) w2s[i] = W2[i];
    __syncthreads();

    int node = blockIdx.x * 16 + (tid >> 4);
    int c = tid & 15;
    if (node >= nrows) return;
    const float* xr = x + (size_t)node * 64;
    float s = 0.f;
#pragma unroll
    for (int k = 0; k < 64; k++) s += xr[k] * w2s[k * 16 + c];
    hs3[(size_t)node * 16 + c] = dinv[node] * s;
}

__global__ void k_final(const float* __restrict__ acc3, const float* __restrict__ hs3,
                        const float* __restrict__ dinv, const float* __restrict__ b2,
                        float* __restrict__ out, int nrows) {
    int n = blockIdx.x * 256 + threadIdx.x;
    if (n >= nrows) return;
    float di = dinv[n];
    const float4* a4 = (const float4*)(acc3 + (size_t)n * 16);
    const float4* h4 = (const float4*)(hs3 + (size_t)n * 16);
    float v[16];
#pragma unroll
    for (int i = 0; i < 4; i++) {
        float4 a = a4[i];
        float4 h = h4[i];
        v[i * 4 + 0] = di * (a.x + h.x) + __ldg(&b2[i * 4 + 0]);
        v[i * 4 + 1] = di * (a.y + h.y) + __ldg(&b2[i * 4 + 1]);
        v[i * 4 + 2] = di * (a.z + h.z) + __ldg(&b2[i * 4 + 2]);
        v[i * 4 + 3] = di * (a.w + h.w) + __ldg(&b2[i * 4 + 3]);
    }
    float mx = v[0];
#pragma unroll
    for (int c = 1; c < 16; c++) mx = fmaxf(mx, v[c]);
    float sum = 0.f;
#pragma unroll
    for (int c = 0; c < 16; c++) sum += expf(v[c] - mx);
    float l = mx + logf(sum);
    float4* o4 = (float4*)(out + (size_t)n * 16);
#pragma unroll
    for (int i = 0; i < 4; i++) {
        float4 o;
        o.x = v[i * 4 + 0] - l;
        o.y = v[i * 4 + 1] - l;
        o.z = v[i * 4 + 2] - l;
        o.w = v[i * 4 + 3] - l;
        o4[i] = o;
    }
}

// ---------------------------------------------------------------------------
// Launch sequence
// ---------------------------------------------------------------------------
extern "C" void kernel_launch(void* const* d_in, const int* in_sizes, int n_in,
                              void* d_out, int out_size) {
    const float* x   = (const float*)d_in[0];
    const int*   ei  = (const int*)d_in[1];
    const float* ew  = (const float*)d_in[2];
    const float* W1  = (const float*)d_in[3];
    const float* b1  = (const float*)d_in[4];
    const float* Wg  = (const float*)d_in[5];
    const float* Wih = (const float*)d_in[6];
    const float* Whh = (const float*)d_in[7];
    const float* bih = (const float*)d_in[8];
    const float* bhh = (const float*)d_in[9];
    const float* W2  = (const float*)d_in[10];
    const float* b2  = (const float*)d_in[11];
    float* out = (float*)d_out;

    const int N = in_sizes[0] / 512;
    const int E = in_sizes[2];
    const int* row = ei;
    const int* col = ei + E;

    float *p_deg, *p_dinv, *p_hs, *p_acc, *p_x, *p_hs3, *p_gi, *p_big, *p_W1T, *p_WB;
    int *p_cnt, *p_start, *p_cursor, *p_csum;
    float2* p_sw;
    cudaGetSymbolAddress((void**)&p_deg,    g_deg);
    cudaGetSymbolAddress((void**)&p_dinv,   g_dinv);
    cudaGetSymbolAddress((void**)&p_hs,     g_hs);
    cudaGetSymbolAddress((void**)&p_acc,    g_acc);
    cudaGetSymbolAddress((void**)&p_x,      g_x);
    cudaGetSymbolAddress((void**)&p_hs3,    g_hs3);
    cudaGetSymbolAddress((void**)&p_gi,     g_gi);
    cudaGetSymbolAddress((void**)&p_big,    g_big);
    cudaGetSymbolAddress((void**)&p_W1T,    g_W1T);
    cudaGetSymbolAddress((void**)&p_WB,     g_WB);
    cudaGetSymbolAddress((void**)&p_cnt,    g_cnt);
    cudaGetSymbolAddress((void**)&p_start,  g_start);
    cudaGetSymbolAddress((void**)&p_cursor, g_cursor);
    cudaGetSymbolAddress((void**)&p_csum,   g_csum);
    cudaGetSymbolAddress((void**)&p_sw,     g_sw);

    cudaFuncSetAttribute(mma_k512, cudaFuncAttributeMaxDynamicSharedMemorySize, K512_SMEM);
    cudaFuncSetAttribute(mma_k64,  cudaFuncAttributeMaxDynamicSharedMemorySize, K64_SMEM);

    const int nblkN   = (N + 255) / 256;
    const int nblkE   = (E + 255) / 256;
    const int nblkM   = (N + 255) / 256;      // BM=256 tiles
    const int nblk16  = (N + 15) / 16;
    const int nchunks = (N + CHUNK - 1) / CHUNK;
    const int nblkG64 = (N * 16 + 255) / 256;
    const int nblkG16 = (N * 4 + 255) / 256;
    const int nblkNF  = (N * 64 + 255) / 256;

    // --- degree / CSR setup ---
    k_init<<<nblkN, 256>>>(p_deg, p_cnt, N);
    k_deg_hist<<<nblkE, 256>>>(col, ew, p_deg, p_cnt, E);
    k_dinv<<<nblkN, 256>>>(p_deg, p_dinv, N);
    k_scan_chunk<<<nchunks, CHUNK>>>(p_cnt, p_start, p_csum, N);
    k_scan_sums<<<1, 32>>>(p_csum, nchunks);
    k_scan_add<<<nblkN, 256>>>(p_start, p_cursor, p_csum, N);
    k_reorder<<<nblkE, 256>>>(row, col, ew, p_cursor, p_sw, E);

    // --- weight prep ---
    k_T512<<<(512 * 64 + 255) / 256, 256>>>(W1, p_W1T);
    k_buildWB<<<(2 * 256 * 64 + 255) / 256, 256>>>(Wg, Whh, p_WB);

    // --- GCN layer 1: hs = dinv*(x@W1); gather fuses relu/dinv/bias ---
    mma_k512<<<nblkM, 256, K512_SMEM>>>((const float4*)x, (const float4*)p_W1T,
                                        p_hs, p_dinv, N);
    gather64<<<nblkG64, 256>>>(p_start, p_cnt, p_sw, (const float4*)p_hs, 16,
                               (const float4*)p_hs, p_dinv, b1, (float4*)p_x, N, 1);

    // --- GatedGraphConv: 2 layers ---
    for (int l = 0; l < 2; l++) {
        // big = x @ [Wg_l | Whh^T]  -> cols 0:64 = m, cols 64:256 = gh
        mma_k64<<<nblkM, 256, K64_SMEM>>>((const float4*)p_x,
                                          (const float4*)(p_WB + (size_t)l * 256 * 64),
                                          p_big, N, 256, 256);
        // agg = scatter(m)  (m strided inside big: 64 float4 per row)
        gather64<<<nblkG64, 256>>>(p_start, p_cnt, p_sw, (const float4*)p_big, 64,
                                   (const float4*)p_big, p_dinv, b1,
                                   (float4*)p_acc, N, 0);
        // gi = agg @ Wih^T   (Wih is [192][64] K-major as-is)
        mma_k64<<<nblkM, 256, K64_SMEM>>>((const float4*)p_acc, (const float4*)Wih,
                                          p_gi, N, 192, 192);
        gru_combine<<<nblkNF, 256>>>(p_gi, p_big, bih, bhh, p_x, N);
    }

    // --- GCN layer 2 + log_softmax ---
    gemm_out16<<<nblk16, 256>>>(p_x, W2, p_dinv, p_hs3, N);
    gather16<<<nblkG16, 256>>>(p_start, p_cnt, p_sw, (const float4*)p_hs3,
                               (float4*)p_acc, N);
    k_final<<<nblkN, 256>>>(p_acc, p_hs3, p_dinv, b2, out, N);
}